// round 1
// baseline (speedup 1.0000x reference)
#include <cuda_runtime.h>

// Problem constants (fixed shapes for this problem instance)
#define D_MODEL 1024
#define NHEAD   16
#define DH      64
#define TSEQ    2048
#define NEG_INF_VAL 1.0e9f

// Scratch: Q, K, V projections and attention output, each [B*T, D] = [4096,1024] fp32.
__device__ float g_Q[4096 * 1024];
__device__ float g_K[4096 * 1024];
__device__ float g_V[4096 * 1024];
__device__ float g_A[4096 * 1024];

// ---------------------------------------------------------------------------
// GEMM: C[M,N] = A[M,K] @ W[N,K]^T + bias[N]
// 64x64 block tile, 256 threads (16x16), 4x4 register tile per thread,
// K staged in chunks of 16 with transposed smem layout [kk][row] so the
// inner loop is pure float4 broadcast / conflict-free LDS.128.
// ---------------------------------------------------------------------------
__global__ __launch_bounds__(256) void gemm_nt_bias(
    const float* __restrict__ A, const float* __restrict__ W,
    const float* __restrict__ bias, float* __restrict__ C,
    int M, int N, int K)
{
    __shared__ float As[16][64];
    __shared__ float Ws[16][64];

    const int bm  = blockIdx.y * 64;
    const int bn  = blockIdx.x * 64;
    const int tid = threadIdx.x;
    const int tx  = tid & 15;        // output col group
    const int ty  = tid >> 4;        // output row group
    const int lrow = tid & 63;       // staging: row within tile
    const int lk4  = (tid >> 6) << 2;// staging: k-offset (4 consecutive k)

    float acc[4][4];
#pragma unroll
    for (int i = 0; i < 4; i++)
#pragma unroll
        for (int j = 0; j < 4; j++) acc[i][j] = 0.0f;

    const float* Ap = A + (size_t)(bm + lrow) * K + lk4;
    const float* Wp = W + (size_t)(bn + lrow) * K + lk4;

    for (int k0 = 0; k0 < K; k0 += 16) {
        float4 a4 = *(const float4*)(Ap + k0);
        float4 w4 = *(const float4*)(Wp + k0);
        As[lk4 + 0][lrow] = a4.x; As[lk4 + 1][lrow] = a4.y;
        As[lk4 + 2][lrow] = a4.z; As[lk4 + 3][lrow] = a4.w;
        Ws[lk4 + 0][lrow] = w4.x; Ws[lk4 + 1][lrow] = w4.y;
        Ws[lk4 + 2][lrow] = w4.z; Ws[lk4 + 3][lrow] = w4.w;
        __syncthreads();

#pragma unroll
        for (int kk = 0; kk < 16; kk++) {
            float4 av = *(const float4*)&As[kk][ty << 2];
            float4 wv = *(const float4*)&Ws[kk][tx << 2];
            float a0 = av.x, a1 = av.y, a2 = av.z, a3 = av.w;
            float w0 = wv.x, w1 = wv.y, w2 = wv.z, w3 = wv.w;
            acc[0][0] += a0 * w0; acc[0][1] += a0 * w1; acc[0][2] += a0 * w2; acc[0][3] += a0 * w3;
            acc[1][0] += a1 * w0; acc[1][1] += a1 * w1; acc[1][2] += a1 * w2; acc[1][3] += a1 * w3;
            acc[2][0] += a2 * w0; acc[2][1] += a2 * w1; acc[2][2] += a2 * w2; acc[2][3] += a2 * w3;
            acc[3][0] += a3 * w0; acc[3][1] += a3 * w1; acc[3][2] += a3 * w2; acc[3][3] += a3 * w3;
        }
        __syncthreads();
    }

    const int col = bn + (tx << 2);
    float4 bv = *(const float4*)&bias[col];
#pragma unroll
    for (int i = 0; i < 4; i++) {
        const int row = bm + (ty << 2) + i;
        float4 r;
        r.x = acc[i][0] + bv.x;
        r.y = acc[i][1] + bv.y;
        r.z = acc[i][2] + bv.z;
        r.w = acc[i][3] + bv.w;
        *(float4*)&C[(size_t)row * N + col] = r;
    }
}

// ---------------------------------------------------------------------------
// Flash attention (fp32). Grid: (T/128, H, B). Block: 128 threads.
// Each thread owns one q row (64 floats in registers) and its o accumulator.
// K/V tiles of 32 keys staged in shared; all smem reads are warp-broadcast.
// Online softmax with running (m, l).
// ---------------------------------------------------------------------------
__global__ __launch_bounds__(128) void attn_kernel(
    const float* __restrict__ Q, const float* __restrict__ K,
    const float* __restrict__ V, const int* __restrict__ mask,
    float* __restrict__ O, int T)
{
    __shared__ float Ks[32 * 64];
    __shared__ float Vs[32 * 64];
    __shared__ int   ms[32];

    const int b   = blockIdx.z;
    const int h   = blockIdx.y;
    const int tid = threadIdx.x;
    const int t   = blockIdx.x * 128 + tid;

    const float* qp = Q + ((size_t)(b * T + t)) * D_MODEL + h * DH;
    float4 q[16];
#pragma unroll
    for (int i = 0; i < 16; i++) q[i] = *(const float4*)(qp + i * 4);

    float4 o[16];
#pragma unroll
    for (int i = 0; i < 16; i++) o[i] = make_float4(0.f, 0.f, 0.f, 0.f);

    float mrow = -3.0e38f;
    float l = 0.0f;
    const float scale = 0.125f; // 1/sqrt(64)

    for (int kt = 0; kt < T; kt += 32) {
        const float* kb = K + ((size_t)(b * T + kt)) * D_MODEL + h * DH;
        const float* vb = V + ((size_t)(b * T + kt)) * D_MODEL + h * DH;
#pragma unroll
        for (int u = 0; u < 4; u++) {
            const int i  = tid + u * 128;  // 0..511 (512 float4 per tile)
            const int j  = i >> 4;
            const int d4 = i & 15;
            ((float4*)Ks)[i] = *(const float4*)(kb + (size_t)j * D_MODEL + d4 * 4);
            ((float4*)Vs)[i] = *(const float4*)(vb + (size_t)j * D_MODEL + d4 * 4);
        }
        if (tid < 32) ms[tid] = mask[b * T + kt + tid];
        __syncthreads();

        float s[32];
        float mt = -3.0e38f;
#pragma unroll
        for (int j = 0; j < 32; j++) {
            const float4* kr = (const float4*)&Ks[j * 64];
            float acc = 0.0f;
#pragma unroll
            for (int d4 = 0; d4 < 16; d4++) {
                float4 kv = kr[d4];
                acc += q[d4].x * kv.x + q[d4].y * kv.y
                     + q[d4].z * kv.z + q[d4].w * kv.w;
            }
            s[j] = (ms[j] != 0) ? acc * scale : -NEG_INF_VAL;
            mt = fmaxf(mt, s[j]);
        }

        const float mnew = fmaxf(mrow, mt);
        const float corr = __expf(mrow - mnew);
        float lsum = 0.0f;
#pragma unroll
        for (int j = 0; j < 32; j++) {
            s[j] = __expf(s[j] - mnew);
            lsum += s[j];
        }
        l = l * corr + lsum;
        mrow = mnew;

#pragma unroll
        for (int i = 0; i < 16; i++) {
            o[i].x *= corr; o[i].y *= corr; o[i].z *= corr; o[i].w *= corr;
        }
#pragma unroll
        for (int j = 0; j < 32; j++) {
            const float p = s[j];
            const float4* vr = (const float4*)&Vs[j * 64];
#pragma unroll
            for (int d4 = 0; d4 < 16; d4++) {
                float4 vv = vr[d4];
                o[d4].x += p * vv.x; o[d4].y += p * vv.y;
                o[d4].z += p * vv.z; o[d4].w += p * vv.w;
            }
        }
        __syncthreads();
    }

    const float inv = 1.0f / l;
    float* op = O + ((size_t)(b * T + t)) * D_MODEL + h * DH;
#pragma unroll
    for (int i = 0; i < 16; i++) {
        float4 r = o[i];
        r.x *= inv; r.y *= inv; r.z *= inv; r.w *= inv;
        *(float4*)(op + i * 4) = r;
    }
}

// ---------------------------------------------------------------------------
// Launch
// ---------------------------------------------------------------------------
extern "C" void kernel_launch(void* const* d_in, const int* in_sizes, int n_in,
                              void* d_out, int out_size)
{
    const float* x    = (const float*)d_in[0];
    const int*   mask = (const int*)  d_in[1];
    const float* Wq   = (const float*)d_in[2];
    const float* bq   = (const float*)d_in[3];
    const float* Wk   = (const float*)d_in[4];
    const float* bk   = (const float*)d_in[5];
    const float* Wv   = (const float*)d_in[6];
    const float* bv   = (const float*)d_in[7];
    const float* Wo   = (const float*)d_in[8];
    const float* bo   = (const float*)d_in[9];
    float* out = (float*)d_out;

    const int D = D_MODEL;
    const int M = in_sizes[0] / D;   // B*T = 4096
    const int T = TSEQ;
    const int B = M / T;

    float *Qp, *Kp, *Vp, *Ap;
    cudaGetSymbolAddress((void**)&Qp, g_Q);
    cudaGetSymbolAddress((void**)&Kp, g_K);
    cudaGetSymbolAddress((void**)&Vp, g_V);
    cudaGetSymbolAddress((void**)&Ap, g_A);

    dim3 ggrid(D / 64, M / 64);     // (16, 64)
    gemm_nt_bias<<<ggrid, 256>>>(x, Wq, bq, Qp, M, D, D);
    gemm_nt_bias<<<ggrid, 256>>>(x, Wk, bk, Kp, M, D, D);
    gemm_nt_bias<<<ggrid, 256>>>(x, Wv, bv, Vp, M, D, D);

    dim3 agrid(T / 128, NHEAD, B);  // (16, 16, 2)
    attn_kernel<<<agrid, 128>>>(Qp, Kp, Vp, mask, Ap, T);

    gemm_nt_bias<<<ggrid, 256>>>(Ap, Wo, bo, out, M, D, D);
}

// round 2
// speedup vs baseline: 3.2970x; 3.2970x over previous
#include <cuda_runtime.h>
#include <cuda_fp16.h>
#include <stdint.h>

#define D_MODEL 1024
#define NHEAD   16
#define DH      64
#define TSEQ    2048

// Pre-split fp16 scratch: value = hi + lo reconstructs ~22-bit mantissa.
// Q,K,V projections and attention output A, each [4096,1024] as (hi,lo) pairs.
__device__ __half g_Qh[4096 * 1024];
__device__ __half g_Ql[4096 * 1024];
__device__ __half g_Kh[4096 * 1024];
__device__ __half g_Kl[4096 * 1024];
__device__ __half g_Vh[4096 * 1024];
__device__ __half g_Vl[4096 * 1024];
__device__ __half g_Ah[4096 * 1024];
__device__ __half g_Al[4096 * 1024];

// ---------------------------------------------------------------------------
// PTX helpers
// ---------------------------------------------------------------------------
__device__ __forceinline__ uint32_t sptr(const void* p) {
    return (uint32_t)__cvta_generic_to_shared(p);
}

__device__ __forceinline__ void ldsm4(uint32_t* r, uint32_t addr) {
    asm volatile("ldmatrix.sync.aligned.m8n8.x4.shared.b16 {%0,%1,%2,%3},[%4];\n"
                 : "=r"(r[0]), "=r"(r[1]), "=r"(r[2]), "=r"(r[3]) : "r"(addr));
}
__device__ __forceinline__ void ldsm4t(uint32_t* r, uint32_t addr) {
    asm volatile("ldmatrix.sync.aligned.m8n8.x4.trans.shared.b16 {%0,%1,%2,%3},[%4];\n"
                 : "=r"(r[0]), "=r"(r[1]), "=r"(r[2]), "=r"(r[3]) : "r"(addr));
}
__device__ __forceinline__ void mma16816(float* c, const uint32_t* a, uint32_t b0, uint32_t b1) {
    asm volatile(
        "mma.sync.aligned.m16n8k16.row.col.f32.f16.f16.f32 "
        "{%0,%1,%2,%3},{%4,%5,%6,%7},{%8,%9},{%0,%1,%2,%3};\n"
        : "+f"(c[0]), "+f"(c[1]), "+f"(c[2]), "+f"(c[3])
        : "r"(a[0]), "r"(a[1]), "r"(a[2]), "r"(a[3]), "r"(b0), "r"(b1));
}

__device__ __forceinline__ uint32_t h2u(__half2 h) { return *(uint32_t*)&h; }

// split fp32 pair -> (hi half2, lo half2)
__device__ __forceinline__ void split2(float x, float y, uint32_t& hr, uint32_t& lr) {
    __half2 h = __floats2half2_rn(x, y);
    __half2 l = __floats2half2_rn(x - __low2float(h), y - __high2float(h));
    hr = h2u(h); lr = h2u(l);
}

// split float4 -> 4+4 halves stored at 8B-aligned smem
__device__ __forceinline__ void split4store(__half* dh, __half* dl, float4 a) {
    uint32_t h01, l01, h23, l23;
    split2(a.x, a.y, h01, l01);
    split2(a.z, a.w, h23, l23);
    *(uint2*)dh = make_uint2(h01, h23);
    *(uint2*)dl = make_uint2(l01, l23);
}

// ---------------------------------------------------------------------------
// GEMM: C[M,N] = A[M,K] @ W[N,K]^T + bias, 3xFP16 split mma.
// BM=128, BN=128, BK=32, 256 threads (8 warps as 4Mx2N, warp tile 32x64).
// PRESPLIT: A comes pre-split (hi/lo fp16); else fp32, split on stage.
// OUTSPLIT: write (hi,lo) fp16 pair scaled by out_scale; else fp32.
// ---------------------------------------------------------------------------
template<int PRESPLIT, int OUTSPLIT>
__global__ __launch_bounds__(256) void gemm_mma(
    const float* __restrict__ Af,
    const __half* __restrict__ Agh, const __half* __restrict__ Agl,
    const float* __restrict__ W, const float* __restrict__ bias,
    float* __restrict__ Cf, __half* __restrict__ Cgh, __half* __restrict__ Cgl,
    int M, int N, int K, float out_scale)
{
    __shared__ __half Ash[128 * 40];
    __shared__ __half Asl[128 * 40];
    __shared__ __half Wsh[128 * 40];
    __shared__ __half Wsl[128 * 40];

    const int tid  = threadIdx.x;
    const int lane = tid & 31;
    const int w    = tid >> 5;
    const int wM   = w >> 1;   // 0..3
    const int wN   = w & 1;    // 0..1
    const int bm   = blockIdx.y * 128;
    const int bn   = blockIdx.x * 128;

    float acc[2][8][4];
#pragma unroll
    for (int mt = 0; mt < 2; mt++)
#pragma unroll
        for (int nt = 0; nt < 8; nt++)
#pragma unroll
            for (int i = 0; i < 4; i++) acc[mt][nt][i] = 0.0f;

    // prefetch registers
    float4 fa[4];        // fp32 A mode
    int4   pah[2], pal[2]; // presplit A mode
    float4 fw[4];        // W always fp32

    // --- load chunk k0 into regs ---
    auto load_regs = [&](int k0) {
        if (PRESPLIT) {
#pragma unroll
            for (int u = 0; u < 2; u++) {
                int i = tid + u * 256;          // 0..511 int4 slots
                int r = i >> 2, v = (i & 3) * 8;
                pah[u] = *(const int4*)&Agh[(bm + r) * K + k0 + v];
                pal[u] = *(const int4*)&Agl[(bm + r) * K + k0 + v];
            }
        } else {
#pragma unroll
            for (int u = 0; u < 4; u++) {
                int i = tid + u * 256;          // 0..1023 float4 slots
                int r = i >> 3, v = (i & 7) * 4;
                fa[u] = *(const float4*)&Af[(bm + r) * K + k0 + v];
            }
        }
#pragma unroll
        for (int u = 0; u < 4; u++) {
            int i = tid + u * 256;
            int r = i >> 3, v = (i & 7) * 4;
            fw[u] = *(const float4*)&W[(bn + r) * K + k0 + v];
        }
    };

    auto store_smem = [&]() {
        if (PRESPLIT) {
#pragma unroll
            for (int u = 0; u < 2; u++) {
                int i = tid + u * 256;
                int r = i >> 2, v = (i & 3) * 8;
                *(int4*)&Ash[r * 40 + v] = pah[u];
                *(int4*)&Asl[r * 40 + v] = pal[u];
            }
        } else {
#pragma unroll
            for (int u = 0; u < 4; u++) {
                int i = tid + u * 256;
                int r = i >> 3, v = (i & 7) * 4;
                split4store(&Ash[r * 40 + v], &Asl[r * 40 + v], fa[u]);
            }
        }
#pragma unroll
        for (int u = 0; u < 4; u++) {
            int i = tid + u * 256;
            int r = i >> 3, v = (i & 7) * 4;
            split4store(&Wsh[r * 40 + v], &Wsl[r * 40 + v], fw[u]);
        }
    };

    load_regs(0);

    for (int k0 = 0; k0 < K; k0 += 32) {
        store_smem();
        __syncthreads();
        if (k0 + 32 < K) load_regs(k0 + 32);  // overlap LDG with mma

#pragma unroll
        for (int ks = 0; ks < 32; ks += 16) {
            uint32_t ah[2][4], al[2][4];
#pragma unroll
            for (int mt = 0; mt < 2; mt++) {
                int r0  = wM * 32 + mt * 16;
                int row = r0 + (lane & 15);
                int col = ks + (lane >> 4) * 8;
                ldsm4(ah[mt], sptr(&Ash[row * 40 + col]));
                ldsm4(al[mt], sptr(&Asl[row * 40 + col]));
            }
            int g = lane >> 3;
#pragma unroll
            for (int p = 0; p < 4; p++) {
                int n0 = wN * 64 + p * 16;
                int rr = n0 + ((g >= 2) ? 8 : 0) + (lane & 7);
                int cc = ks + ((g & 1) ? 8 : 0);
                uint32_t bh[4], bl[4];
                ldsm4(bh, sptr(&Wsh[rr * 40 + cc]));
                ldsm4(bl, sptr(&Wsl[rr * 40 + cc]));
#pragma unroll
                for (int mt = 0; mt < 2; mt++) {
                    mma16816(acc[mt][2 * p],     ah[mt], bh[0], bh[1]);
                    mma16816(acc[mt][2 * p],     ah[mt], bl[0], bl[1]);
                    mma16816(acc[mt][2 * p],     al[mt], bh[0], bh[1]);
                    mma16816(acc[mt][2 * p + 1], ah[mt], bh[2], bh[3]);
                    mma16816(acc[mt][2 * p + 1], ah[mt], bl[2], bl[3]);
                    mma16816(acc[mt][2 * p + 1], al[mt], bh[2], bh[3]);
                }
            }
        }
        __syncthreads();
    }

    // epilogue
#pragma unroll
    for (int mt = 0; mt < 2; mt++) {
#pragma unroll
        for (int nt = 0; nt < 8; nt++) {
            int row = bm + wM * 32 + mt * 16 + (lane >> 2);
            int col = bn + wN * 64 + nt * 8 + 2 * (lane & 3);
            float b0 = bias[col], b1 = bias[col + 1];
            float v00 = (acc[mt][nt][0] + b0) * out_scale;
            float v01 = (acc[mt][nt][1] + b1) * out_scale;
            float v10 = (acc[mt][nt][2] + b0) * out_scale;
            float v11 = (acc[mt][nt][3] + b1) * out_scale;
            if (OUTSPLIT) {
                uint32_t h0, l0, h1, l1;
                split2(v00, v01, h0, l0);
                split2(v10, v11, h1, l1);
                *(uint32_t*)&Cgh[row * N + col]       = h0;
                *(uint32_t*)&Cgl[row * N + col]       = l0;
                *(uint32_t*)&Cgh[(row + 8) * N + col] = h1;
                *(uint32_t*)&Cgl[(row + 8) * N + col] = l1;
            } else {
                *(float2*)&Cf[row * N + col]       = make_float2(v00, v01);
                *(float2*)&Cf[(row + 8) * N + col] = make_float2(v10, v11);
            }
        }
    }
}

// ---------------------------------------------------------------------------
// Flash attention with 3xFP16 mma. Block: 256 thr (8 warps), BQ=128 (16 q/warp),
// KV chunk 64. Q scale (1/8) pre-folded into Qh/Ql by the projection epilogue.
// ---------------------------------------------------------------------------
__global__ __launch_bounds__(256) void attn_mma(
    const __half* __restrict__ Qh, const __half* __restrict__ Ql,
    const __half* __restrict__ Kh, const __half* __restrict__ Kl,
    const __half* __restrict__ Vh, const __half* __restrict__ Vl,
    const int* __restrict__ mask,
    __half* __restrict__ Aoh, __half* __restrict__ Aol, int T)
{
    __shared__ __half Ksh[64 * 72];
    __shared__ __half Ksl[64 * 72];
    __shared__ __half Vsh[64 * 72];
    __shared__ __half Vsl[64 * 72];
    __shared__ int    ms[64];

    const int tid  = threadIdx.x;
    const int lane = tid & 31;
    const int w    = tid >> 5;
    const int b    = blockIdx.z;
    const int h    = blockIdx.y;
    const int q0   = blockIdx.x * 128;

    // Q fragments (A-operand, k=dh), loaded straight from gmem (pairs are 4B)
    const int qrow = b * T + q0 + w * 16 + (lane >> 2);
    const int qcol = h * 64 + 2 * (lane & 3);
    uint32_t qfh[4][4], qfl[4][4];
#pragma unroll
    for (int kt = 0; kt < 4; kt++) {
        int c = qcol + kt * 16;
        qfh[kt][0] = *(const uint32_t*)&Qh[qrow * 1024 + c];
        qfh[kt][1] = *(const uint32_t*)&Qh[(qrow + 8) * 1024 + c];
        qfh[kt][2] = *(const uint32_t*)&Qh[qrow * 1024 + c + 8];
        qfh[kt][3] = *(const uint32_t*)&Qh[(qrow + 8) * 1024 + c + 8];
        qfl[kt][0] = *(const uint32_t*)&Ql[qrow * 1024 + c];
        qfl[kt][1] = *(const uint32_t*)&Ql[(qrow + 8) * 1024 + c];
        qfl[kt][2] = *(const uint32_t*)&Ql[qrow * 1024 + c + 8];
        qfl[kt][3] = *(const uint32_t*)&Ql[(qrow + 8) * 1024 + c + 8];
    }

    float o[8][4];
#pragma unroll
    for (int nt = 0; nt < 8; nt++)
#pragma unroll
        for (int i = 0; i < 4; i++) o[nt][i] = 0.0f;
    float m0 = -3.0e38f, m1 = -3.0e38f, l0 = 0.0f, l1 = 0.0f;

    for (int kv0 = 0; kv0 < T; kv0 += 64) {
        // stage K/V chunk (64 rows x 64 halves per array)
#pragma unroll
        for (int u = 0; u < 2; u++) {
            int i = tid + u * 256;       // 0..511 int4 slots
            int r = i >> 3, v = (i & 7) * 8;
            int gidx = (b * T + kv0 + r) * 1024 + h * 64 + v;
            *(int4*)&Ksh[r * 72 + v] = *(const int4*)&Kh[gidx];
            *(int4*)&Ksl[r * 72 + v] = *(const int4*)&Kl[gidx];
            *(int4*)&Vsh[r * 72 + v] = *(const int4*)&Vh[gidx];
            *(int4*)&Vsl[r * 72 + v] = *(const int4*)&Vl[gidx];
        }
        if (tid < 64) ms[tid] = mask[b * T + kv0 + tid];
        __syncthreads();

        // S = Q K^T  (3x split)
        float s[8][4];
#pragma unroll
        for (int nt = 0; nt < 8; nt++)
#pragma unroll
            for (int i = 0; i < 4; i++) s[nt][i] = 0.0f;

        const int g = lane >> 3;
#pragma unroll
        for (int kt = 0; kt < 4; kt++) {
#pragma unroll
            for (int p = 0; p < 4; p++) {
                int rr = p * 16 + ((g >= 2) ? 8 : 0) + (lane & 7);  // key row
                int cc = kt * 16 + ((g & 1) ? 8 : 0);               // d col
                uint32_t bh[4], bl[4];
                ldsm4(bh, sptr(&Ksh[rr * 72 + cc]));
                ldsm4(bl, sptr(&Ksl[rr * 72 + cc]));
                mma16816(s[2 * p],     qfh[kt], bh[0], bh[1]);
                mma16816(s[2 * p],     qfh[kt], bl[0], bl[1]);
                mma16816(s[2 * p],     qfl[kt], bh[0], bh[1]);
                mma16816(s[2 * p + 1], qfh[kt], bh[2], bh[3]);
                mma16816(s[2 * p + 1], qfh[kt], bl[2], bl[3]);
                mma16816(s[2 * p + 1], qfl[kt], bh[2], bh[3]);
            }
        }

        // mask + online softmax
        float mt0 = -3.0e38f, mt1 = -3.0e38f;
#pragma unroll
        for (int nt = 0; nt < 8; nt++) {
            int kc = nt * 8 + 2 * (lane & 3);
            if (ms[kc] == 0)     { s[nt][0] = -1.0e9f; s[nt][2] = -1.0e9f; }
            if (ms[kc + 1] == 0) { s[nt][1] = -1.0e9f; s[nt][3] = -1.0e9f; }
            mt0 = fmaxf(mt0, fmaxf(s[nt][0], s[nt][1]));
            mt1 = fmaxf(mt1, fmaxf(s[nt][2], s[nt][3]));
        }
        mt0 = fmaxf(mt0, __shfl_xor_sync(0xffffffffu, mt0, 1));
        mt0 = fmaxf(mt0, __shfl_xor_sync(0xffffffffu, mt0, 2));
        mt1 = fmaxf(mt1, __shfl_xor_sync(0xffffffffu, mt1, 1));
        mt1 = fmaxf(mt1, __shfl_xor_sync(0xffffffffu, mt1, 2));

        float mn0 = fmaxf(m0, mt0), mn1 = fmaxf(m1, mt1);
        float c0 = __expf(m0 - mn0), c1 = __expf(m1 - mn1);
        m0 = mn0; m1 = mn1;

        float ls0 = 0.0f, ls1 = 0.0f;
#pragma unroll
        for (int nt = 0; nt < 8; nt++) {
            s[nt][0] = __expf(s[nt][0] - mn0);
            s[nt][1] = __expf(s[nt][1] - mn0);
            s[nt][2] = __expf(s[nt][2] - mn1);
            s[nt][3] = __expf(s[nt][3] - mn1);
            ls0 += s[nt][0] + s[nt][1];
            ls1 += s[nt][2] + s[nt][3];
        }
        l0 = l0 * c0 + ls0;
        l1 = l1 * c1 + ls1;
#pragma unroll
        for (int nt = 0; nt < 8; nt++) {
            o[nt][0] *= c0; o[nt][1] *= c0;
            o[nt][2] *= c1; o[nt][3] *= c1;
        }

        // O += P V  (3x split; P split on the fly)
#pragma unroll
        for (int kt = 0; kt < 4; kt++) {
            uint32_t ph[4], pl[4];
            split2(s[2 * kt][0],     s[2 * kt][1],     ph[0], pl[0]);
            split2(s[2 * kt][2],     s[2 * kt][3],     ph[1], pl[1]);
            split2(s[2 * kt + 1][0], s[2 * kt + 1][1], ph[2], pl[2]);
            split2(s[2 * kt + 1][2], s[2 * kt + 1][3], ph[3], pl[3]);
#pragma unroll
            for (int p = 0; p < 4; p++) {
                int rr = kt * 16 + ((g & 1) ? 8 : 0) + (lane & 7);  // key row
                int cc = p * 16 + ((g >= 2) ? 8 : 0);               // d col
                uint32_t bh[4], bl[4];
                ldsm4t(bh, sptr(&Vsh[rr * 72 + cc]));
                ldsm4t(bl, sptr(&Vsl[rr * 72 + cc]));
                mma16816(o[2 * p],     ph, bh[0], bh[1]);
                mma16816(o[2 * p],     ph, bl[0], bl[1]);
                mma16816(o[2 * p],     pl, bh[0], bh[1]);
                mma16816(o[2 * p + 1], ph, bh[2], bh[3]);
                mma16816(o[2 * p + 1], ph, bl[2], bl[3]);
                mma16816(o[2 * p + 1], pl, bh[2], bh[3]);
            }
        }
        __syncthreads();
    }

    // finalize: l reduce across the 4-lane row group, normalize, split-store
    l0 += __shfl_xor_sync(0xffffffffu, l0, 1);
    l0 += __shfl_xor_sync(0xffffffffu, l0, 2);
    l1 += __shfl_xor_sync(0xffffffffu, l1, 1);
    l1 += __shfl_xor_sync(0xffffffffu, l1, 2);
    float inv0 = 1.0f / l0, inv1 = 1.0f / l1;

    const int orow = b * T + q0 + w * 16 + (lane >> 2);
    const int ocol = h * 64 + 2 * (lane & 3);
#pragma unroll
    for (int nt = 0; nt < 8; nt++) {
        int c = ocol + nt * 8;
        uint32_t h0, lo0, h1, lo1;
        split2(o[nt][0] * inv0, o[nt][1] * inv0, h0, lo0);
        split2(o[nt][2] * inv1, o[nt][3] * inv1, h1, lo1);
        *(uint32_t*)&Aoh[orow * 1024 + c]       = h0;
        *(uint32_t*)&Aol[orow * 1024 + c]       = lo0;
        *(uint32_t*)&Aoh[(orow + 8) * 1024 + c] = h1;
        *(uint32_t*)&Aol[(orow + 8) * 1024 + c] = lo1;
    }
}

// ---------------------------------------------------------------------------
// Launch
// ---------------------------------------------------------------------------
extern "C" void kernel_launch(void* const* d_in, const int* in_sizes, int n_in,
                              void* d_out, int out_size)
{
    const float* x    = (const float*)d_in[0];
    const int*   mask = (const int*)  d_in[1];
    const float* Wq   = (const float*)d_in[2];
    const float* bq   = (const float*)d_in[3];
    const float* Wk   = (const float*)d_in[4];
    const float* bk   = (const float*)d_in[5];
    const float* Wv   = (const float*)d_in[6];
    const float* bv   = (const float*)d_in[7];
    const float* Wo   = (const float*)d_in[8];
    const float* bo   = (const float*)d_in[9];
    float* out = (float*)d_out;

    const int D = D_MODEL;
    const int M = in_sizes[0] / D;   // 4096
    const int T = TSEQ;
    const int B = M / T;

    __half *Qh, *Ql, *Kh, *Kl, *Vh, *Vl, *Ah, *Al;
    cudaGetSymbolAddress((void**)&Qh, g_Qh);
    cudaGetSymbolAddress((void**)&Ql, g_Ql);
    cudaGetSymbolAddress((void**)&Kh, g_Kh);
    cudaGetSymbolAddress((void**)&Kl, g_Kl);
    cudaGetSymbolAddress((void**)&Vh, g_Vh);
    cudaGetSymbolAddress((void**)&Vl, g_Vl);
    cudaGetSymbolAddress((void**)&Ah, g_Ah);
    cudaGetSymbolAddress((void**)&Al, g_Al);

    dim3 ggrid(D / 128, M / 128);   // (8, 32)

    // projections -> pre-split fp16 (Q pre-scaled by 1/sqrt(dh) = 0.125)
    gemm_mma<0, 1><<<ggrid, 256>>>(x, nullptr, nullptr, Wq, bq,
                                   nullptr, Qh, Ql, M, D, D, 0.125f);
    gemm_mma<0, 1><<<ggrid, 256>>>(x, nullptr, nullptr, Wk, bk,
                                   nullptr, Kh, Kl, M, D, D, 1.0f);
    gemm_mma<0, 1><<<ggrid, 256>>>(x, nullptr, nullptr, Wv, bv,
                                   nullptr, Vh, Vl, M, D, D, 1.0f);

    dim3 agrid(T / 128, NHEAD, B);  // (16, 16, 2)
    attn_mma<<<agrid, 256>>>(Qh, Ql, Kh, Kl, Vh, Vl, mask, Ah, Al, T);

    // output projection: pre-split A input, fp32 output
    gemm_mma<1, 0><<<ggrid, 256>>>(nullptr, Ah, Al, Wo, bo,
                                   out, nullptr, nullptr, M, D, D, 1.0f);
}